// round 17
// baseline (speedup 1.0000x reference)
#include <cuda_runtime.h>

#define NB 8
#define NS 4096
#define NH 8
#define ND 128
#define ROW (NH * ND)                 // 1024 floats per token-row
#define VPR (ROW / 4)                 // 256 float4 per row
#define MAX_TOTAL (NB * NS)           // 32768 rows per cache
#define CACHE_F (MAX_TOTAL * ROW)     // floats per cache
#define CACHE_V (MAX_TOTAL * VPR)     // 8388608 float4 per cache
#define TOTAL_V (2 * CACHE_V)         // 16777216 float4
#define THREADS 512
#define F4_PER_WARP 128               // 4 float4 per thread, warp-interleaved
#define WARPS_PER_BLOCK (THREADS / 32)
#define BLOCKS (TOTAL_V / (F4_PER_WARP * WARPS_PER_BLOCK))   // 8192
#define FULL 0xffffffffu

// Final-config kernel with the last untested knob: 512-thread blocks
// (identical per-warp tile/access pattern to the 57.8us best; predicted
// neutral — the kernel is HBM turnaround-bound at ~80% of spec with traffic
// at the mandatory floor).
//
// Barrier-free: every warp independently loads seq_lens (32B coalesced,
// L1-hit after the first warp per SM), shuffle-scans the cumsum, resolves
// its batch via SHFL broadcasts, then streams its half token-row: lane l
// handles base + {0,32,64,96} + l. Fully coalesced LDG.128 (.cs) with 4
// independent loads in flight per thread; STG.128 (.wt) bulk stores.
__global__ void __launch_bounds__(THREADS) pack_kernel(
    const float4* __restrict__ k_src,
    const float4* __restrict__ v_src,
    const int* __restrict__ seq_lens,
    float4* __restrict__ out)
{
    const int lane = threadIdx.x & 31;

    // per-warp cumsum: lane i (i<8) ends with v = sum(seq_lens[0..i])
    int sl = (lane < NB) ? __ldg(seq_lens + lane) : 0;
    int v = sl;
    #pragma unroll
    for (int off = 1; off < NB; off <<= 1) {
        int n = __shfl_up_sync(FULL, v, off);
        if (lane >= off) v += n;
    }
    const int total = __shfl_sync(FULL, v, NB - 1);

    const int gw   = blockIdx.x * WARPS_PER_BLOCK + (threadIdx.x >> 5);
    const int base = gw * F4_PER_WARP;            // warp's first float4 index

    const int which = (base >= CACHE_V) ? 1 : 0;  // whole warp in one cache
    const int j   = base - which * CACHE_V;
    const int row = j >> 8;                        // token-row (shared by all 4 elems)
    const int col = (j & (VPR - 1)) + lane;        // 0 or 128, plus lane

    float4 v0, v1, v2, v3;
    if (row < total) {
        // batch search + offset via shuffle broadcasts of the scan
        int bt = row;                              // t = row - cs[b], cs[0] = 0
        int bi = 0;
        #pragma unroll
        for (int bb = 1; bb < NB; bb++) {
            int csb = __shfl_sync(FULL, v, bb - 1);
            if (row >= csb) { bi = bb; bt = row - csb; }
        }
        const float4* src = (which ? v_src : k_src)
                          + (long long)(bi * NS + bt) * VPR + col;
        v0 = __ldcs(src +  0);
        v1 = __ldcs(src + 32);
        v2 = __ldcs(src + 64);
        v3 = __ldcs(src + 96);
    } else {
        v0 = v1 = v2 = v3 = make_float4(0.f, 0.f, 0.f, 0.f);
    }

    float4* dst = out + base + lane;
    __stwt(dst +  0, v0);
    __stwt(dst + 32, v1);
    __stwt(dst + 64, v2);
    __stwt(dst + 96, v3);

    // scalar tail outputs (block 0, warp 0) — after the bulk stores
    if (blockIdx.x == 0 && threadIdx.x < 32) {
        float* seq_out = (float*)out + 2 * (long long)CACHE_F;  // [NB]
        float* cum_out = seq_out + NB;                           // [NB+1]
        if (lane < NB) {
            seq_out[lane] = (float)sl;
            cum_out[lane + 1] = (float)v;
        }
        if (lane == 0) cum_out[0] = 0.0f;
    }
}

extern "C" void kernel_launch(void* const* d_in, const int* in_sizes, int n_in,
                              void* d_out, int out_size) {
    const float4* key_states   = (const float4*)d_in[0];
    const float4* value_states = (const float4*)d_in[1];
    const int*    seq_lens     = (const int*)d_in[2];

    pack_kernel<<<BLOCKS, THREADS>>>(key_states, value_states, seq_lens,
                                     (float4*)d_out);
}